// round 2
// baseline (speedup 1.0000x reference)
#include <cuda_runtime.h>
#include <cstdint>

#define NB   1024
#define NK   5
#define NV   32000
#define ND   128

// ---------------- scratch (device globals; no allocation allowed) ----------
__device__ float g_vi_embed[NB * ND];   // [1024,128] fp32 accumulator
__device__ float g_pos[NB];             // pos dot per b
__device__ float g_negacc[NB * NK];     // neg dots per (b,k)

// ---------------- helpers ----------------------------------------------------
// fp32 -> tf32 round-to-nearest (unbiased; HW mma truncates, so pre-round)
static __device__ __forceinline__ float to_tf32(float x) {
    uint32_t r;
    asm("cvt.rna.tf32.f32 %0, %1;" : "=r"(r) : "f"(x));
    return __uint_as_float(r);
}

static __device__ __forceinline__ void mma_tf32(
    float c[4], uint32_t a0, uint32_t a1, uint32_t a2, uint32_t a3,
    uint32_t b0, uint32_t b1)
{
    asm volatile(
        "mma.sync.aligned.m16n8k8.row.col.f32.tf32.tf32.f32 "
        "{%0,%1,%2,%3}, {%4,%5,%6,%7}, {%8,%9}, {%0,%1,%2,%3};"
        : "+f"(c[0]), "+f"(c[1]), "+f"(c[2]), "+f"(c[3])
        : "r"(a0), "r"(a1), "r"(a2), "r"(a3), "r"(b0), "r"(b1));
}

static __device__ __forceinline__ uint32_t fbits(float x) { return __float_as_uint(x); }

// smem strides (floats), chosen for conflict-free fragment loads:
//   A loads: addr = row*SA + tig      -> (4g+tig)  mod 32 bijective for SA=132
//   B loads (GEMM1, [k][n]): addr = k*SB + g -> (8tig+g) mod 32 bijective for SB=136
//   B loads (GEMM2, [v][d]): addr = v*SA + tig -> (4g+tig) bijective for SA=132
#define SA 132
#define SB 136

static constexpr int SMEM1 = (128 * SA + 128 * SB) * 4;   // 137216 B
static constexpr int SMEM2 = (2 * 128 * SA) * 4;          // 135168 B

// ---------------- kernel 0: zero scratch ------------------------------------
__global__ void zero_kernel() {
    int i = blockIdx.x * blockDim.x + threadIdx.x;
    if (i < NB * ND) g_vi_embed[i] = 0.0f;
    if (i < NB)      g_pos[i] = 0.0f;
    if (i < NB * NK) g_negacc[i] = 0.0f;
}

// ---------------- kernel 1: vi_embed = vi @ V  (split-K, mma.sync tf32) -----
// grid (8 m-tiles, 50 k-splits); each CTA: 5 K-chunks of 128; atomicAdd output.
__global__ void __launch_bounds__(256, 1)
gemm1_kernel(const float* __restrict__ vi, const float* __restrict__ Vm)
{
    extern __shared__ float sm[];
    float* As = sm;              // [128][SA]  A = vi chunk   (row=m, col=k)
    float* Bs = sm + 128 * SA;   // [128][SB]  B = V  chunk   (row=k, col=n)

    const int tid  = threadIdx.x;
    const int wid  = tid >> 5;
    const int lane = tid & 31;
    const int g    = lane >> 2;       // group id (0..7)
    const int tig  = lane & 3;        // thread-in-group (0..3)
    const int m0   = blockIdx.x * 128;
    const int wrow = wid * 16;        // warp's 16-row strip within the tile

    float acc[16][4];
    #pragma unroll
    for (int nt = 0; nt < 16; nt++)
        #pragma unroll
        for (int j = 0; j < 4; j++) acc[nt][j] = 0.0f;

    for (int it = 0; it < 5; it++) {
        const size_t k0 = (size_t)(blockIdx.y * 5 + it) * 128;

        // A tile: vi[m0+r][k0+c], natural row-major
        #pragma unroll
        for (int i = tid; i < 128 * 32; i += 256) {
            int r = i >> 5;
            int c = (i & 31) << 2;
            float4 v = *(const float4*)(vi + (size_t)(m0 + r) * NV + k0 + c);
            v.x = to_tf32(v.x); v.y = to_tf32(v.y); v.z = to_tf32(v.z); v.w = to_tf32(v.w);
            *(float4*)(As + r * SA + c) = v;
        }
        // B tile: V[k0+r][c], natural row-major [k][n]
        #pragma unroll
        for (int i = tid; i < 128 * 32; i += 256) {
            int r = i >> 5;
            int c = (i & 31) << 2;
            float4 v = *(const float4*)(Vm + (k0 + r) * ND + c);
            v.x = to_tf32(v.x); v.y = to_tf32(v.y); v.z = to_tf32(v.z); v.w = to_tf32(v.w);
            *(float4*)(Bs + r * SB + c) = v;
        }
        __syncthreads();

        #pragma unroll
        for (int ks = 0; ks < 16; ks++) {
            const int kb = ks * 8;
            uint32_t a0 = fbits(As[(wrow + g)     * SA + kb + tig]);
            uint32_t a1 = fbits(As[(wrow + g + 8) * SA + kb + tig]);
            uint32_t a2 = fbits(As[(wrow + g)     * SA + kb + tig + 4]);
            uint32_t a3 = fbits(As[(wrow + g + 8) * SA + kb + tig + 4]);
            const float* brow0 = Bs + (kb + tig)     * SB + g;
            const float* brow1 = Bs + (kb + tig + 4) * SB + g;
            #pragma unroll
            for (int nt = 0; nt < 16; nt++) {
                uint32_t b0 = fbits(brow0[nt * 8]);
                uint32_t b1 = fbits(brow1[nt * 8]);
                mma_tf32(acc[nt], a0, a1, a2, a3, b0, b1);
            }
        }
        __syncthreads();
    }

    // epilogue: atomic-accumulate split-K partials into g_vi_embed
    float* dst0 = g_vi_embed + (size_t)(m0 + wrow + g) * ND + 2 * tig;
    float* dst1 = dst0 + 8 * ND;
    #pragma unroll
    for (int nt = 0; nt < 16; nt++) {
        atomicAdd(dst0 + nt * 8,     acc[nt][0]);
        atomicAdd(dst0 + nt * 8 + 1, acc[nt][1]);
        atomicAdd(dst1 + nt * 8,     acc[nt][2]);
        atomicAdd(dst1 + nt * 8 + 1, acc[nt][3]);
    }
}

// ---------------- kernel 2: w = vi_embed @ U^T, fused vo/neg reductions -----
// grid (8 m-tiles, 250 v-tiles). w tile [128b x 128v] lives only in registers.
__global__ void __launch_bounds__(256, 1)
gemm2_kernel(const float* __restrict__ vo, const float* __restrict__ neg,
             const float* __restrict__ U)
{
    extern __shared__ float sm[];
    float* As = sm;              // [128][SA]  A = vi_embed  (row=b, col=d)
    float* Bs = sm + 128 * SA;   // [128][SA]  B = U tile    (row=v, col=d)

    const int tid  = threadIdx.x;
    const int wid  = tid >> 5;
    const int lane = tid & 31;
    const int g    = lane >> 2;
    const int tig  = lane & 3;
    const int m0   = blockIdx.y * 128;
    const int v0   = blockIdx.x * 128;
    const int wrow = wid * 16;

    // A tile: vi_embed[m0+r][c]
    #pragma unroll
    for (int i = tid; i < 128 * 32; i += 256) {
        int r = i >> 5;
        int c = (i & 31) << 2;
        float4 v = *(const float4*)(g_vi_embed + (size_t)(m0 + r) * ND + c);
        v.x = to_tf32(v.x); v.y = to_tf32(v.y); v.z = to_tf32(v.z); v.w = to_tf32(v.w);
        *(float4*)(As + r * SA + c) = v;
    }
    // B tile: U[v0+r][c], natural row-major [v][d]  (k-major per n: perfect for row.col)
    #pragma unroll
    for (int i = tid; i < 128 * 32; i += 256) {
        int r = i >> 5;
        int c = (i & 31) << 2;
        float4 v = *(const float4*)(U + (size_t)(v0 + r) * ND + c);
        v.x = to_tf32(v.x); v.y = to_tf32(v.y); v.z = to_tf32(v.z); v.w = to_tf32(v.w);
        *(float4*)(Bs + r * SA + c) = v;
    }
    __syncthreads();

    float acc[16][4];
    #pragma unroll
    for (int nt = 0; nt < 16; nt++)
        #pragma unroll
        for (int j = 0; j < 4; j++) acc[nt][j] = 0.0f;

    #pragma unroll
    for (int ks = 0; ks < 16; ks++) {
        const int kb = ks * 8;
        uint32_t a0 = fbits(As[(wrow + g)     * SA + kb + tig]);
        uint32_t a1 = fbits(As[(wrow + g + 8) * SA + kb + tig]);
        uint32_t a2 = fbits(As[(wrow + g)     * SA + kb + tig + 4]);
        uint32_t a3 = fbits(As[(wrow + g + 8) * SA + kb + tig + 4]);
        #pragma unroll
        for (int nt = 0; nt < 16; nt++) {
            uint32_t b0 = fbits(Bs[(nt * 8 + g) * SA + kb + tig]);
            uint32_t b1 = fbits(Bs[(nt * 8 + g) * SA + kb + tig + 4]);
            mma_tf32(acc[nt], a0, a1, a2, a3, b0, b1);
        }
    }

    // fused epilogue: w stays in acc registers.
    // thread owns rows r0, r1 and cols v0 + nt*8 + 2*tig + {0,1}
    const int r0 = m0 + wrow + g;
    const int r1 = r0 + 8;
    const int cb = v0 + 2 * tig;

    {
        const float* p0 = vo + (size_t)r0 * NV + cb;
        const float* p1 = vo + (size_t)r1 * NV + cb;
        float s0 = 0.0f, s1 = 0.0f;
        #pragma unroll
        for (int nt = 0; nt < 16; nt++) {
            float2 t0 = *(const float2*)(p0 + nt * 8);
            float2 t1 = *(const float2*)(p1 + nt * 8);
            s0 += t0.x * acc[nt][0] + t0.y * acc[nt][1];
            s1 += t1.x * acc[nt][2] + t1.y * acc[nt][3];
        }
        s0 += __shfl_xor_sync(0xFFFFFFFFu, s0, 1);
        s0 += __shfl_xor_sync(0xFFFFFFFFu, s0, 2);
        s1 += __shfl_xor_sync(0xFFFFFFFFu, s1, 1);
        s1 += __shfl_xor_sync(0xFFFFFFFFu, s1, 2);
        if (tig == 0) {
            atomicAdd(&g_pos[r0], s0);
            atomicAdd(&g_pos[r1], s1);
        }
    }

    #pragma unroll
    for (int k = 0; k < NK; k++) {
        const float* p0 = neg + ((size_t)r0 * NK + k) * NV + cb;
        const float* p1 = neg + ((size_t)r1 * NK + k) * NV + cb;
        float s0 = 0.0f, s1 = 0.0f;
        #pragma unroll
        for (int nt = 0; nt < 16; nt++) {
            float2 t0 = *(const float2*)(p0 + nt * 8);
            float2 t1 = *(const float2*)(p1 + nt * 8);
            s0 += t0.x * acc[nt][0] + t0.y * acc[nt][1];
            s1 += t1.x * acc[nt][2] + t1.y * acc[nt][3];
        }
        s0 += __shfl_xor_sync(0xFFFFFFFFu, s0, 1);
        s0 += __shfl_xor_sync(0xFFFFFFFFu, s0, 2);
        s1 += __shfl_xor_sync(0xFFFFFFFFu, s1, 1);
        s1 += __shfl_xor_sync(0xFFFFFFFFu, s1, 2);
        if (tig == 0) {
            atomicAdd(&g_negacc[r0 * NK + k], s0);
            atomicAdd(&g_negacc[r1 * NK + k], s1);
        }
    }
}

// ---------------- kernel 3: logsigmoid + mean -------------------------------
static __device__ __forceinline__ float logsig(float x) {
    float z = -fabsf(x);
    float l = log1pf(__expf(z));
    return (x >= 0.0f) ? -l : (x - l);
}

__global__ void finalize_kernel(float* __restrict__ out)
{
    __shared__ float red[1024];
    int b = threadIdx.x;
    float l = logsig(g_pos[b]);
    #pragma unroll
    for (int k = 0; k < NK; k++)
        l += logsig(-g_negacc[b * NK + k]);
    red[b] = -l;
    __syncthreads();
    #pragma unroll
    for (int s = 512; s > 0; s >>= 1) {
        if (b < s) red[b] += red[b + s];
        __syncthreads();
    }
    if (b == 0) out[0] = red[0] * (1.0f / (float)NB);
}

// ---------------- launch -----------------------------------------------------
extern "C" void kernel_launch(void* const* d_in, const int* in_sizes, int n_in,
                              void* d_out, int out_size)
{
    const float* vi  = (const float*)d_in[0];
    const float* vo  = (const float*)d_in[1];
    const float* neg = (const float*)d_in[2];
    const float* Vm  = (const float*)d_in[3];
    const float* U   = (const float*)d_in[4];
    float* out = (float*)d_out;

    cudaFuncSetAttribute(gemm1_kernel, cudaFuncAttributeMaxDynamicSharedMemorySize, SMEM1);
    cudaFuncSetAttribute(gemm2_kernel, cudaFuncAttributeMaxDynamicSharedMemorySize, SMEM2);

    zero_kernel<<<(NB * ND + 255) / 256, 256>>>();
    gemm1_kernel<<<dim3(8, 50), 256, SMEM1>>>(vi, Vm);
    gemm2_kernel<<<dim3(250, 8), 256, SMEM2>>>(vo, neg, U);
    finalize_kernel<<<1, 1024>>>(out);
}

// round 3
// speedup vs baseline: 1.1410x; 1.1410x over previous
#include <cuda_runtime.h>
#include <cstdint>

#define NB   1024
#define NK   5
#define NV   32000
#define ND   128

// ---------------- scratch (device globals; no allocation allowed) ----------
__device__ float g_vi_embed[NB * ND];   // [1024,128] fp32 accumulator
__device__ float g_pos[NB];             // pos dot per b
__device__ float g_negacc[NB * NK];     // neg dots per (b,k)

// ---------------- helpers ----------------------------------------------------
static __device__ __forceinline__ float to_tf32(float x) {
    uint32_t r;
    asm("cvt.rna.tf32.f32 %0, %1;" : "=r"(r) : "f"(x));
    return __uint_as_float(r);
}
// pack two fp32 -> bf16x2 (lo = first elem, hi = second), round-to-nearest
static __device__ __forceinline__ uint32_t pack_bf16x2(float lo, float hi) {
    uint32_t r;
    asm("cvt.rn.bf16x2.f32 %0, %1, %2;" : "=r"(r) : "f"(hi), "f"(lo));
    return r;
}

static __device__ __forceinline__ void mma_tf32(
    float c[4], uint32_t a0, uint32_t a1, uint32_t a2, uint32_t a3,
    uint32_t b0, uint32_t b1)
{
    asm volatile(
        "mma.sync.aligned.m16n8k8.row.col.f32.tf32.tf32.f32 "
        "{%0,%1,%2,%3}, {%4,%5,%6,%7}, {%8,%9}, {%0,%1,%2,%3};"
        : "+f"(c[0]), "+f"(c[1]), "+f"(c[2]), "+f"(c[3])
        : "r"(a0), "r"(a1), "r"(a2), "r"(a3), "r"(b0), "r"(b1));
}

static __device__ __forceinline__ void mma_bf16(
    float c[4], uint32_t a0, uint32_t a1, uint32_t a2, uint32_t a3,
    uint32_t b0, uint32_t b1)
{
    asm volatile(
        "mma.sync.aligned.m16n8k16.row.col.f32.bf16.bf16.f32 "
        "{%0,%1,%2,%3}, {%4,%5,%6,%7}, {%8,%9}, {%0,%1,%2,%3};"
        : "+f"(c[0]), "+f"(c[1]), "+f"(c[2]), "+f"(c[3])
        : "r"(a0), "r"(a1), "r"(a2), "r"(a3), "r"(b0), "r"(b1));
}

static __device__ __forceinline__ uint32_t fbits(float x) { return __float_as_uint(x); }

// ---------------- kernel 0: zero scratch ------------------------------------
__global__ void zero_kernel() {
    int i = blockIdx.x * blockDim.x + threadIdx.x;
    if (i < NB * ND) g_vi_embed[i] = 0.0f;
    if (i < NB)      g_pos[i] = 0.0f;
    if (i < NB * NK) g_negacc[i] = 0.0f;
}

// ---------------- kernel 1: vi_embed = vi @ V  (tf32, split-K, pipelined) ---
// grid (8 m-tiles, 50 k-splits); per CTA: 10 chunks of k=64, register-staged
// pipeline (LDG chunk i+1 overlaps compute of chunk i). atomicAdd output.
//
// smem strides (fp32 words/row): A: 68 (68%32=4 -> 4g+tig bank-bijective)
//                                B: 136 (136%32=8 -> 8tig+g bank-bijective)
#define S1A 68
#define S1B 136
static constexpr int SMEM1 = (128 * S1A + 64 * S1B) * 4;   // 69632 B

__global__ void __launch_bounds__(256, 1)
gemm1_kernel(const float* __restrict__ vi, const float* __restrict__ Vm)
{
    extern __shared__ float sm[];
    float* As = sm;               // [128][S1A]  vi chunk (row=m, col=k)
    float* Bs = sm + 128 * S1A;   // [64][S1B]   V  chunk (row=k, col=n)

    const int tid  = threadIdx.x;
    const int wid  = tid >> 5;
    const int lane = tid & 31;
    const int g    = lane >> 2;
    const int tig  = lane & 3;
    const int m0   = blockIdx.x * 128;
    const int wrow = wid * 16;
    const size_t kbase = (size_t)blockIdx.y * 640;

    float acc[16][4];
    #pragma unroll
    for (int nt = 0; nt < 16; nt++)
        #pragma unroll
        for (int j = 0; j < 4; j++) acc[nt][j] = 0.0f;

    float4 ra[8], rb[8];

    // A tile: 128 rows x 16 float4; B tile: 64 rows x 32 float4
    const int ar = tid >> 4, ac = (tid & 15) << 2;       // +16 rows per step
    const int br = tid >> 5, bc = (tid & 31) << 2;       // +8 rows per step

    #define G1_LDG(IT)                                                          \
        do {                                                                    \
            size_t k0 = kbase + (size_t)(IT) * 64;                              \
            _Pragma("unroll")                                                   \
            for (int t = 0; t < 8; t++)                                         \
                ra[t] = *(const float4*)(vi + (size_t)(m0 + ar + t * 16) * NV + k0 + ac); \
            _Pragma("unroll")                                                   \
            for (int t = 0; t < 8; t++)                                         \
                rb[t] = *(const float4*)(Vm + (k0 + br + t * 8) * ND + bc);     \
        } while (0)

    #define G1_STS()                                                            \
        do {                                                                    \
            _Pragma("unroll")                                                   \
            for (int t = 0; t < 8; t++) {                                       \
                float4 v = ra[t];                                               \
                v.x = to_tf32(v.x); v.y = to_tf32(v.y);                         \
                v.z = to_tf32(v.z); v.w = to_tf32(v.w);                         \
                *(float4*)(As + (ar + t * 16) * S1A + ac) = v;                  \
            }                                                                   \
            _Pragma("unroll")                                                   \
            for (int t = 0; t < 8; t++) {                                       \
                float4 v = rb[t];                                               \
                v.x = to_tf32(v.x); v.y = to_tf32(v.y);                         \
                v.z = to_tf32(v.z); v.w = to_tf32(v.w);                         \
                *(float4*)(Bs + (br + t * 8) * S1B + bc) = v;                   \
            }                                                                   \
        } while (0)

    G1_LDG(0);
    G1_STS();
    __syncthreads();

    for (int it = 0; it < 10; it++) {
        if (it + 1 < 10) G1_LDG(it + 1);

        #pragma unroll
        for (int ks = 0; ks < 8; ks++) {
            const int kb = ks * 8;
            uint32_t a0 = fbits(As[(wrow + g)     * S1A + kb + tig]);
            uint32_t a1 = fbits(As[(wrow + g + 8) * S1A + kb + tig]);
            uint32_t a2 = fbits(As[(wrow + g)     * S1A + kb + tig + 4]);
            uint32_t a3 = fbits(As[(wrow + g + 8) * S1A + kb + tig + 4]);
            const float* brow0 = Bs + (kb + tig)     * S1B + g;
            const float* brow1 = Bs + (kb + tig + 4) * S1B + g;
            #pragma unroll
            for (int nt = 0; nt < 16; nt++) {
                uint32_t b0 = fbits(brow0[nt * 8]);
                uint32_t b1 = fbits(brow1[nt * 8]);
                mma_tf32(acc[nt], a0, a1, a2, a3, b0, b1);
            }
        }

        if (it + 1 < 10) {
            __syncthreads();
            G1_STS();
            __syncthreads();
        }
    }

    // epilogue: atomic-accumulate split-K partials
    float* dst0 = g_vi_embed + (size_t)(m0 + wrow + g) * ND + 2 * tig;
    float* dst1 = dst0 + 8 * ND;
    #pragma unroll
    for (int nt = 0; nt < 16; nt++) {
        atomicAdd(dst0 + nt * 8,     acc[nt][0]);
        atomicAdd(dst0 + nt * 8 + 1, acc[nt][1]);
        atomicAdd(dst1 + nt * 8,     acc[nt][2]);
        atomicAdd(dst1 + nt * 8 + 1, acc[nt][3]);
    }
}

// ---------------- kernel 2: w = vi_embed @ U^T (bf16), fused reductions -----
// grid (8 m-tiles, 250 v-tiles), x=m fastest so 8 concurrent m-CTAs share each
// U v-tile through L2. w tile [128b x 128v] lives only in registers.
//
// bf16 tiles: row stride 68 u32 words (136 bf16) -> 4g+tig bank-bijective.
#define S2W 68
static constexpr int SMEM2 = 2 * 128 * S2W * 4;   // 69632 B

__global__ void __launch_bounds__(256, 1)
gemm2_kernel(const float* __restrict__ vo, const float* __restrict__ neg,
             const float* __restrict__ U)
{
    extern __shared__ uint32_t sm2[];
    uint32_t* As = sm2;              // [128][S2W] bf16x2: vi_embed (row=b, col=d)
    uint32_t* Bs = sm2 + 128 * S2W;  // [128][S2W] bf16x2: U        (row=v, col=d)

    const int tid  = threadIdx.x;
    const int wid  = tid >> 5;
    const int lane = tid & 31;
    const int g    = lane >> 2;
    const int tig  = lane & 3;
    const int m0   = blockIdx.x * 128;
    const int v0   = blockIdx.y * 128;
    const int wrow = wid * 16;

    // load + convert tiles: each thread 16 float4 per tile (warp = 1 row)
    #pragma unroll
    for (int t = 0; t < 16; t++) {
        int r = wid + t * 8;
        int c4 = lane;  // float4 col
        float4 v = *(const float4*)(g_vi_embed + (size_t)(m0 + r) * ND + c4 * 4);
        As[r * S2W + c4 * 2]     = pack_bf16x2(v.x, v.y);
        As[r * S2W + c4 * 2 + 1] = pack_bf16x2(v.z, v.w);
    }
    #pragma unroll
    for (int t = 0; t < 16; t++) {
        int r = wid + t * 8;
        int c4 = lane;
        float4 v = *(const float4*)(U + (size_t)(v0 + r) * ND + c4 * 4);
        Bs[r * S2W + c4 * 2]     = pack_bf16x2(v.x, v.y);
        Bs[r * S2W + c4 * 2 + 1] = pack_bf16x2(v.z, v.w);
    }
    __syncthreads();

    // prefetch vo epilogue data (addresses independent of acc) to overlap MMA
    const int r0 = m0 + wrow + g;
    const int r1 = r0 + 8;
    const int cb = v0 + 2 * tig;
    float2 pv0[16], pv1[16];
    {
        const float* p0 = vo + (size_t)r0 * NV + cb;
        const float* p1 = vo + (size_t)r1 * NV + cb;
        #pragma unroll
        for (int nt = 0; nt < 16; nt++) {
            pv0[nt] = *(const float2*)(p0 + nt * 8);
            pv1[nt] = *(const float2*)(p1 + nt * 8);
        }
    }

    float acc[16][4];
    #pragma unroll
    for (int nt = 0; nt < 16; nt++)
        #pragma unroll
        for (int j = 0; j < 4; j++) acc[nt][j] = 0.0f;

    #pragma unroll
    for (int ks = 0; ks < 8; ks++) {
        const int kb = ks * 8;   // u32-word offset (16 bf16 per step)
        uint32_t a0 = As[(wrow + g)     * S2W + kb + tig];
        uint32_t a1 = As[(wrow + g + 8) * S2W + kb + tig];
        uint32_t a2 = As[(wrow + g)     * S2W + kb + tig + 4];
        uint32_t a3 = As[(wrow + g + 8) * S2W + kb + tig + 4];
        #pragma unroll
        for (int nt = 0; nt < 16; nt++) {
            uint32_t b0 = Bs[(nt * 8 + g) * S2W + kb + tig];
            uint32_t b1 = Bs[(nt * 8 + g) * S2W + kb + tig + 4];
            mma_bf16(acc[nt], a0, a1, a2, a3, b0, b1);
        }
    }

    // fused epilogue: w stays in acc registers
    {
        float s0 = 0.0f, s1 = 0.0f;
        #pragma unroll
        for (int nt = 0; nt < 16; nt++) {
            s0 += pv0[nt].x * acc[nt][0] + pv0[nt].y * acc[nt][1];
            s1 += pv1[nt].x * acc[nt][2] + pv1[nt].y * acc[nt][3];
        }
        s0 += __shfl_xor_sync(0xFFFFFFFFu, s0, 1);
        s0 += __shfl_xor_sync(0xFFFFFFFFu, s0, 2);
        s1 += __shfl_xor_sync(0xFFFFFFFFu, s1, 1);
        s1 += __shfl_xor_sync(0xFFFFFFFFu, s1, 2);
        if (tig == 0) {
            atomicAdd(&g_pos[r0], s0);
            atomicAdd(&g_pos[r1], s1);
        }
    }

    #pragma unroll
    for (int k = 0; k < NK; k++) {
        const float* p0 = neg + ((size_t)r0 * NK + k) * NV + cb;
        const float* p1 = neg + ((size_t)r1 * NK + k) * NV + cb;
        float s0 = 0.0f, s1 = 0.0f;
        #pragma unroll
        for (int nt = 0; nt < 16; nt++) {
            float2 t0 = *(const float2*)(p0 + nt * 8);
            float2 t1 = *(const float2*)(p1 + nt * 8);
            s0 += t0.x * acc[nt][0] + t0.y * acc[nt][1];
            s1 += t1.x * acc[nt][2] + t1.y * acc[nt][3];
        }
        s0 += __shfl_xor_sync(0xFFFFFFFFu, s0, 1);
        s0 += __shfl_xor_sync(0xFFFFFFFFu, s0, 2);
        s1 += __shfl_xor_sync(0xFFFFFFFFu, s1, 1);
        s1 += __shfl_xor_sync(0xFFFFFFFFu, s1, 2);
        if (tig == 0) {
            atomicAdd(&g_negacc[r0 * NK + k], s0);
            atomicAdd(&g_negacc[r1 * NK + k], s1);
        }
    }
}

// ---------------- kernel 3: logsigmoid + mean (shfl reduction) --------------
static __device__ __forceinline__ float logsig(float x) {
    float z = -fabsf(x);
    float l = log1pf(__expf(z));
    return (x >= 0.0f) ? -l : (x - l);
}

__global__ void finalize_kernel(float* __restrict__ out)
{
    __shared__ float red[32];
    int b = threadIdx.x;
    float l = logsig(g_pos[b]);
    #pragma unroll
    for (int k = 0; k < NK; k++)
        l += logsig(-g_negacc[b * NK + k]);
    float v = -l;
    #pragma unroll
    for (int o = 16; o > 0; o >>= 1) v += __shfl_xor_sync(0xFFFFFFFFu, v, o);
    if ((b & 31) == 0) red[b >> 5] = v;
    __syncthreads();
    if (b < 32) {
        float s = red[b];
        #pragma unroll
        for (int o = 16; o > 0; o >>= 1) s += __shfl_xor_sync(0xFFFFFFFFu, s, o);
        if (b == 0) out[0] = s * (1.0f / (float)NB);
    }
}

// ---------------- launch -----------------------------------------------------
extern "C" void kernel_launch(void* const* d_in, const int* in_sizes, int n_in,
                              void* d_out, int out_size)
{
    const float* vi  = (const float*)d_in[0];
    const float* vo  = (const float*)d_in[1];
    const float* neg = (const float*)d_in[2];
    const float* Vm  = (const float*)d_in[3];
    const float* U   = (const float*)d_in[4];
    float* out = (float*)d_out;

    cudaFuncSetAttribute(gemm1_kernel, cudaFuncAttributeMaxDynamicSharedMemorySize, SMEM1);
    cudaFuncSetAttribute(gemm2_kernel, cudaFuncAttributeMaxDynamicSharedMemorySize, SMEM2);

    zero_kernel<<<(NB * ND + 255) / 256, 256>>>();
    gemm1_kernel<<<dim3(8, 50), 256, SMEM1>>>(vi, Vm);
    gemm2_kernel<<<dim3(8, 250), 256, SMEM2>>>(vo, neg, U);
    finalize_kernel<<<1, 1024>>>(out);
}

// round 4
// speedup vs baseline: 1.2147x; 1.0645x over previous
#include <cuda_runtime.h>
#include <cstdint>

#define NB   1024
#define NK   5
#define NV   32000
#define ND   128

// ---------------- scratch (device globals; no allocation allowed) ----------
__device__ float g_vi_embed[NB * ND];   // [1024,128] fp32 accumulator
__device__ float g_pos[NB];             // pos dot per b
__device__ float g_negacc[NB * NK];     // neg dots per (b,k)

// ---------------- helpers ----------------------------------------------------
// pack two fp32 -> bf16x2 (lo = first elem, hi = second), round-to-nearest
static __device__ __forceinline__ uint32_t pack_bf16x2(float lo, float hi) {
    uint32_t r;
    asm("cvt.rn.bf16x2.f32 %0, %1, %2;" : "=r"(r) : "f"(hi), "f"(lo));
    return r;
}

static __device__ __forceinline__ void mma_bf16(
    float c[4], uint32_t a0, uint32_t a1, uint32_t a2, uint32_t a3,
    uint32_t b0, uint32_t b1)
{
    asm volatile(
        "mma.sync.aligned.m16n8k16.row.col.f32.bf16.bf16.f32 "
        "{%0,%1,%2,%3}, {%4,%5,%6,%7}, {%8,%9}, {%0,%1,%2,%3};"
        : "+f"(c[0]), "+f"(c[1]), "+f"(c[2]), "+f"(c[3])
        : "r"(a0), "r"(a1), "r"(a2), "r"(a3), "r"(b0), "r"(b1));
}

// ---------------- kernel 0: zero scratch ------------------------------------
__global__ void zero_kernel() {
    int i = blockIdx.x * blockDim.x + threadIdx.x;
    if (i < NB * ND) g_vi_embed[i] = 0.0f;
    if (i < NB)      g_pos[i] = 0.0f;
    if (i < NB * NK) g_negacc[i] = 0.0f;
}

// ---------------- kernel 1: vi_embed = vi @ V  (bf16, split-K, pipelined) ---
// grid (8 m-tiles, 50 k-splits); per CTA: 10 chunks of k=64, register-staged
// pipeline (LDG chunk i+1 overlaps compute of chunk i). atomicAdd output.
//
// A smem: bf16x2 words, stride 36 (36%32=4 -> 4g+tig bank-bijective)
// B smem: fp32 [k][n], stride 132 (132%32=4 -> 8tig+4d+g bank-bijective)
#define G1SA 36
#define G1SB 132
static constexpr int SMEM1 = 128 * G1SA * 4 + 64 * G1SB * 4;   // 52224 B

__global__ void __launch_bounds__(256, 1)
gemm1_kernel(const float* __restrict__ vi, const float* __restrict__ Vm)
{
    extern __shared__ float sm[];
    uint32_t* Aw = (uint32_t*)sm;        // [128][G1SA]  vi chunk bf16x2 (row=m)
    float*    Bs = sm + 128 * G1SA;      // [64][G1SB]   V  chunk fp32   (row=k)

    const int tid  = threadIdx.x;
    const int wid  = tid >> 5;
    const int lane = tid & 31;
    const int g    = lane >> 2;
    const int tig  = lane & 3;
    const int m0   = blockIdx.x * 128;
    const int wrow = wid * 16;
    const size_t kbase = (size_t)blockIdx.y * 640;

    float acc[16][4];
    #pragma unroll
    for (int nt = 0; nt < 16; nt++)
        #pragma unroll
        for (int j = 0; j < 4; j++) acc[nt][j] = 0.0f;

    float4 ra[8], rb[8];
    const int ar = tid >> 4, ac4 = tid & 15;     // A: 16 float4/row, +16 rows/step
    const int br = tid >> 5, bc = (tid & 31) << 2; // B: 32 float4/row, +8 rows/step

    #define G1_LDG(IT)                                                           \
        do {                                                                     \
            size_t k0 = kbase + (size_t)(IT) * 64;                               \
            _Pragma("unroll")                                                    \
            for (int t = 0; t < 8; t++)                                          \
                ra[t] = *(const float4*)(vi + (size_t)(m0 + ar + t * 16) * NV + k0 + ac4 * 4); \
            _Pragma("unroll")                                                    \
            for (int t = 0; t < 8; t++)                                          \
                rb[t] = *(const float4*)(Vm + (k0 + br + t * 8) * ND + bc);      \
        } while (0)

    #define G1_STS()                                                             \
        do {                                                                     \
            _Pragma("unroll")                                                    \
            for (int t = 0; t < 8; t++) {                                        \
                uint2 p;                                                         \
                p.x = pack_bf16x2(ra[t].x, ra[t].y);                             \
                p.y = pack_bf16x2(ra[t].z, ra[t].w);                             \
                *(uint2*)(Aw + (ar + t * 16) * G1SA + ac4 * 2) = p;              \
            }                                                                    \
            _Pragma("unroll")                                                    \
            for (int t = 0; t < 8; t++)                                          \
                *(float4*)(Bs + (br + t * 8) * G1SB + bc) = rb[t];               \
        } while (0)

    G1_LDG(0);
    G1_STS();
    __syncthreads();

    for (int it = 0; it < 10; it++) {
        if (it + 1 < 10) G1_LDG(it + 1);

        #pragma unroll
        for (int ks = 0; ks < 4; ks++) {            // k16 steps over k=64
            const int kw = ks * 8;
            uint32_t a0 = Aw[(wrow + g)     * G1SA + kw + tig];
            uint32_t a1 = Aw[(wrow + g + 8) * G1SA + kw + tig];
            uint32_t a2 = Aw[(wrow + g)     * G1SA + kw + tig + 4];
            uint32_t a3 = Aw[(wrow + g + 8) * G1SA + kw + tig + 4];
            const float* bp0 = Bs + (ks * 16 + 2 * tig)     * G1SB + g;
            const float* bp1 = bp0 + G1SB;
            const float* bp8 = Bs + (ks * 16 + 2 * tig + 8) * G1SB + g;
            const float* bp9 = bp8 + G1SB;
            #pragma unroll
            for (int nt = 0; nt < 16; nt++) {
                uint32_t b0 = pack_bf16x2(bp0[nt * 8], bp1[nt * 8]);
                uint32_t b1 = pack_bf16x2(bp8[nt * 8], bp9[nt * 8]);
                mma_bf16(acc[nt], a0, a1, a2, a3, b0, b1);
            }
        }

        if (it + 1 < 10) {
            __syncthreads();
            G1_STS();
            __syncthreads();
        }
    }

    // epilogue: atomic-accumulate split-K partials
    float* dst0 = g_vi_embed + (size_t)(m0 + wrow + g) * ND + 2 * tig;
    float* dst1 = dst0 + 8 * ND;
    #pragma unroll
    for (int nt = 0; nt < 16; nt++) {
        atomicAdd(dst0 + nt * 8,     acc[nt][0]);
        atomicAdd(dst0 + nt * 8 + 1, acc[nt][1]);
        atomicAdd(dst1 + nt * 8,     acc[nt][2]);
        atomicAdd(dst1 + nt * 8 + 1, acc[nt][3]);
    }
}

// ---------------- kernel 2: w = vi_embed @ U^T (bf16), fused reductions -----
// grid (8 m-tiles, 250 v-tiles), x=m fastest -> 8 concurrent m-CTAs share each
// U v-tile via L2. nt-outer mainloop: acc is 4 regs, stream loads for nt+1
// prefetched while nt's MMAs run. 2 CTAs/SM for cross-CTA phase overlap.
#define S2W 68
static constexpr int SMEM2 = 2 * 128 * S2W * 4;   // 69632 B

__global__ void __launch_bounds__(256, 2)
gemm2_kernel(const float* __restrict__ vo, const float* __restrict__ neg,
             const float* __restrict__ U)
{
    extern __shared__ uint32_t sm2[];
    uint32_t* As = sm2;              // [128][S2W] bf16x2: vi_embed (row=b)
    uint32_t* Bs = sm2 + 128 * S2W;  // [128][S2W] bf16x2: U        (row=v)

    const int tid  = threadIdx.x;
    const int wid  = tid >> 5;
    const int lane = tid & 31;
    const int g    = lane >> 2;
    const int tig  = lane & 3;
    const int m0   = blockIdx.x * 128;
    const int v0   = blockIdx.y * 128;
    const int wrow = wid * 16;

    // tile load + bf16 pack (warp-per-row, 16 rows per warp)
    #pragma unroll
    for (int t = 0; t < 16; t++) {
        int r = wid + t * 8;
        float4 v = *(const float4*)(g_vi_embed + (size_t)(m0 + r) * ND + lane * 4);
        As[r * S2W + lane * 2]     = pack_bf16x2(v.x, v.y);
        As[r * S2W + lane * 2 + 1] = pack_bf16x2(v.z, v.w);
    }
    #pragma unroll
    for (int t = 0; t < 16; t++) {
        int r = wid + t * 8;
        float4 v = *(const float4*)(U + (size_t)(v0 + r) * ND + lane * 4);
        Bs[r * S2W + lane * 2]     = pack_bf16x2(v.x, v.y);
        Bs[r * S2W + lane * 2 + 1] = pack_bf16x2(v.z, v.w);
    }
    __syncthreads();

    // cache A fragments for all 8 k-steps (32 regs)
    uint32_t af[8][4];
    #pragma unroll
    for (int ks = 0; ks < 8; ks++) {
        const int kw = ks * 8;
        af[ks][0] = As[(wrow + g)     * S2W + kw + tig];
        af[ks][1] = As[(wrow + g + 8) * S2W + kw + tig];
        af[ks][2] = As[(wrow + g)     * S2W + kw + tig + 4];
        af[ks][3] = As[(wrow + g + 8) * S2W + kw + tig + 4];
    }

    const int r0 = m0 + wrow + g;
    const int r1 = r0 + 8;
    const int cb = v0 + 2 * tig;
    const float* vp0 = vo + (size_t)r0 * NV + cb;
    const float* vp1 = vo + (size_t)r1 * NV + cb;
    const float* np0 = neg + (size_t)r0 * NK * NV + cb;
    const float* np1 = neg + (size_t)r1 * NK * NV + cb;

    // prime stream buffers for nt=0
    float2 cv0 = *(const float2*)(vp0);
    float2 cv1 = *(const float2*)(vp1);
    float2 cn0[NK], cn1[NK];
    #pragma unroll
    for (int k = 0; k < NK; k++) {
        cn0[k] = *(const float2*)(np0 + (size_t)k * NV);
        cn1[k] = *(const float2*)(np1 + (size_t)k * NV);
    }

    float sp0 = 0.0f, sp1 = 0.0f;
    float sn0[NK], sn1[NK];
    #pragma unroll
    for (int k = 0; k < NK; k++) { sn0[k] = 0.0f; sn1[k] = 0.0f; }

    #pragma unroll
    for (int nt = 0; nt < 16; nt++) {
        // prefetch nt+1 stream data under this nt's MMAs
        float2 xv0, xv1, xn0[NK], xn1[NK];
        if (nt < 15) {
            const int off = (nt + 1) * 8;
            xv0 = *(const float2*)(vp0 + off);
            xv1 = *(const float2*)(vp1 + off);
            #pragma unroll
            for (int k = 0; k < NK; k++) {
                xn0[k] = *(const float2*)(np0 + (size_t)k * NV + off);
                xn1[k] = *(const float2*)(np1 + (size_t)k * NV + off);
            }
        }

        float a4[4] = {0.0f, 0.0f, 0.0f, 0.0f};
        #pragma unroll
        for (int ks = 0; ks < 8; ks++) {
            uint32_t b0 = Bs[(nt * 8 + g) * S2W + ks * 8 + tig];
            uint32_t b1 = Bs[(nt * 8 + g) * S2W + ks * 8 + tig + 4];
            mma_bf16(a4, af[ks][0], af[ks][1], af[ks][2], af[ks][3], b0, b1);
        }

        sp0 += cv0.x * a4[0] + cv0.y * a4[1];
        sp1 += cv1.x * a4[2] + cv1.y * a4[3];
        #pragma unroll
        for (int k = 0; k < NK; k++) {
            sn0[k] += cn0[k].x * a4[0] + cn0[k].y * a4[1];
            sn1[k] += cn1[k].x * a4[2] + cn1[k].y * a4[3];
        }

        if (nt < 15) {
            cv0 = xv0; cv1 = xv1;
            #pragma unroll
            for (int k = 0; k < NK; k++) { cn0[k] = xn0[k]; cn1[k] = xn1[k]; }
        }
    }

    // reduce over tig (4 lanes share a row-pair), then atomics
    #pragma unroll
    for (int o = 1; o <= 2; o <<= 1) {
        sp0 += __shfl_xor_sync(0xFFFFFFFFu, sp0, o);
        sp1 += __shfl_xor_sync(0xFFFFFFFFu, sp1, o);
        #pragma unroll
        for (int k = 0; k < NK; k++) {
            sn0[k] += __shfl_xor_sync(0xFFFFFFFFu, sn0[k], o);
            sn1[k] += __shfl_xor_sync(0xFFFFFFFFu, sn1[k], o);
        }
    }
    if (tig == 0) {
        atomicAdd(&g_pos[r0], sp0);
        atomicAdd(&g_pos[r1], sp1);
        #pragma unroll
        for (int k = 0; k < NK; k++) {
            atomicAdd(&g_negacc[r0 * NK + k], sn0[k]);
            atomicAdd(&g_negacc[r1 * NK + k], sn1[k]);
        }
    }
}

// ---------------- kernel 3: logsigmoid + mean (shfl reduction) --------------
static __device__ __forceinline__ float logsig(float x) {
    float z = -fabsf(x);
    float l = log1pf(__expf(z));
    return (x >= 0.0f) ? -l : (x - l);
}

__global__ void finalize_kernel(float* __restrict__ out)
{
    __shared__ float red[32];
    int b = threadIdx.x;
    float l = logsig(g_pos[b]);
    #pragma unroll
    for (int k = 0; k < NK; k++)
        l += logsig(-g_negacc[b * NK + k]);
    float v = -l;
    #pragma unroll
    for (int o = 16; o > 0; o >>= 1) v += __shfl_xor_sync(0xFFFFFFFFu, v, o);
    if ((b & 31) == 0) red[b >> 5] = v;
    __syncthreads();
    if (b < 32) {
        float s = red[b];
        #pragma unroll
        for (int o = 16; o > 0; o >>= 1) s += __shfl_xor_sync(0xFFFFFFFFu, s, o);
        if (b == 0) out[0] = s * (1.0f / (float)NB);
    }
}

// ---------------- launch -----------------------------------------------------
extern "C" void kernel_launch(void* const* d_in, const int* in_sizes, int n_in,
                              void* d_out, int out_size)
{
    const float* vi  = (const float*)d_in[0];
    const float* vo  = (const float*)d_in[1];
    const float* neg = (const float*)d_in[2];
    const float* Vm  = (const float*)d_in[3];
    const float* U   = (const float*)d_in[4];
    float* out = (float*)d_out;

    cudaFuncSetAttribute(gemm1_kernel, cudaFuncAttributeMaxDynamicSharedMemorySize, SMEM1);
    cudaFuncSetAttribute(gemm2_kernel, cudaFuncAttributeMaxDynamicSharedMemorySize, SMEM2);

    zero_kernel<<<(NB * ND + 255) / 256, 256>>>();
    gemm1_kernel<<<dim3(8, 50), 256, SMEM1>>>(vi, Vm);
    gemm2_kernel<<<dim3(8, 250), 256, SMEM2>>>(vo, neg, U);
    finalize_kernel<<<1, 1024>>>(out);
}